// round 13
// baseline (speedup 1.0000x reference)
#include <cuda_runtime.h>
#include <cuda_fp16.h>
#include <cstdint>

#define B_ 2
#define L_ 512
#define V_ 64
#define D_ 128
#define NC_ 8
#define NR_MAX 96

// ---- static device scratch (no allocations allowed) ----
__device__ float  g_sumK[B_ * L_ * D_];
__device__ __half g_sKh[B_ * L_ * D_];
__device__ __half g_sKl[B_ * L_ * D_];
__device__ int    g_idx[B_][NC_][L_];
__device__ int    g_cnt[B_][NC_];

#define SCALE_ 0.08838834764831845f

__device__ __forceinline__ uint32_t packh2(float a, float b2) {
    __half2 h = __halves2half2(__float2half_rn(a), __float2half_rn(b2));
    return *reinterpret_cast<uint32_t*>(&h);
}

// ===========================================================================
// Prep kernel: blocks [0,1024) sumK (+fp16 hi/lo); [1024,1040) idx lists
// ===========================================================================
__global__ void prep_kernel(const float4* __restrict__ key4,
                            const int* __restrict__ label) {
    __shared__ float4 part[256];
    const int blk = blockIdx.x;

    if (blk < 1024) {
        int bl = blk;
        int g = threadIdx.x & 31, qd = threadIdx.x >> 5;
        const float4* p = key4 + (size_t)bl * (V_ * D_ / 4)
                        + (size_t)(qd * 8) * (D_ / 4) + g;
        float4 s = make_float4(0.f, 0.f, 0.f, 0.f);
#pragma unroll
        for (int vv = 0; vv < 8; vv++) {
            float4 t = p[(size_t)vv * (D_ / 4)];
            s.x += t.x; s.y += t.y; s.z += t.z; s.w += t.w;
        }
        part[threadIdx.x] = s;
        __syncthreads();
        if (qd < 4) {
            float4 a = part[threadIdx.x], b2 = part[threadIdx.x + 128];
            part[threadIdx.x] =
                make_float4(a.x + b2.x, a.y + b2.y, a.z + b2.z, a.w + b2.w);
        }
        __syncthreads();
        if (qd == 0) {
            float4 a = part[g], b2 = part[32 + g], c2 = part[64 + g], d2 = part[96 + g];
            float4 r = make_float4(a.x + b2.x + c2.x + d2.x, a.y + b2.y + c2.y + d2.y,
                                   a.z + b2.z + c2.z + d2.z, a.w + b2.w + c2.w + d2.w);
            ((float4*)g_sumK)[(size_t)bl * 32 + g] = r;
            __half hx = __float2half_rn(r.x), hy = __float2half_rn(r.y);
            __half hz = __float2half_rn(r.z), hw = __float2half_rn(r.w);
            size_t o = (size_t)bl * 64 + g * 2;
            { __half2 t = __halves2half2(hx, hy); ((uint32_t*)g_sKh)[o] = *(uint32_t*)&t; }
            { __half2 t = __halves2half2(hz, hw); ((uint32_t*)g_sKh)[o + 1] = *(uint32_t*)&t; }
            ((uint32_t*)g_sKl)[o] =
                packh2(r.x - __half2float(hx), r.y - __half2float(hy));
            ((uint32_t*)g_sKl)[o + 1] =
                packh2(r.z - __half2float(hz), r.w - __half2float(hw));
        }
    } else {
        if (threadIdx.x >= 32) return;
        int bc = blk - 1024;
        int c = bc & 7, b = bc >> 3;
        int lane = threadIdx.x;
        int cnt = 0;
        for (int l0 = 0; l0 < L_; l0 += 32) {
            int l = l0 + lane;
            int lbl = label[b * L_ + l];
            unsigned m = __ballot_sync(0xffffffffu, lbl == c);
            if (lbl == c) {
                int pos = cnt + __popc(m & ((1u << lane) - 1u));
                g_idx[b][c][pos] = l;
            }
            cnt += __popc(m);
        }
        if (lane == 0) g_cnt[b][c] = cnt;
    }
}

// ===========================================================================
// PTX helpers (family-common, valid on target sm_103)
// ===========================================================================
__device__ __forceinline__ uint32_t smem_u32(const void* p) {
    uint32_t a;
    asm("{ .reg .u64 t; cvta.to.shared.u64 t, %1; cvt.u32.u64 %0, t; }"
        : "=r"(a) : "l"(p));
    return a;
}
__device__ __forceinline__ void cpa16(uint32_t dst, const void* src) {
    asm volatile("cp.async.cg.shared.global [%0], [%1], 16;"
                 :: "r"(dst), "l"(src));
}
__device__ __forceinline__ void ldsm4(uint32_t addr, uint32_t* r) {
    asm volatile("ldmatrix.sync.aligned.m8n8.x4.shared.b16 {%0,%1,%2,%3}, [%4];"
                 : "=r"(r[0]), "=r"(r[1]), "=r"(r[2]), "=r"(r[3]) : "r"(addr));
}
__device__ __forceinline__ void ldsm4t(uint32_t addr, uint32_t* r) {
    asm volatile("ldmatrix.sync.aligned.m8n8.x4.trans.shared.b16 {%0,%1,%2,%3}, [%4];"
                 : "=r"(r[0]), "=r"(r[1]), "=r"(r[2]), "=r"(r[3]) : "r"(addr));
}
__device__ __forceinline__ void mma16816(float* c, const uint32_t* a,
                                         uint32_t b0, uint32_t b1) {
    asm volatile(
        "mma.sync.aligned.m16n8k16.row.col.f32.f16.f16.f32 "
        "{%0,%1,%2,%3}, {%4,%5,%6,%7}, {%8,%9}, {%0,%1,%2,%3};"
        : "+f"(c[0]), "+f"(c[1]), "+f"(c[2]), "+f"(c[3])
        : "r"(a[0]), "r"(a[1]), "r"(a[2]), "r"(a[3]), "r"(b0), "r"(b1));
}
__device__ __forceinline__ void split2(float x0, float x1,
                                       uint32_t& hi, uint32_t& lo) {
    __half h0 = __float2half_rn(x0), h1 = __float2half_rn(x1);
    __half l0 = __float2half_rn(x0 - __half2float(h0));
    __half l1 = __float2half_rn(x1 - __half2float(h1));
    __half2 hp = __halves2half2(h0, h1), lp = __halves2half2(l0, l1);
    hi = *reinterpret_cast<uint32_t*>(&hp);
    lo = *reinterpret_cast<uint32_t*>(&lp);
}
// byte offset in an f16 tile (256B rows), 16B-chunk XOR swizzle
__device__ __forceinline__ uint32_t swz(int row, int col) {
    return (uint32_t)(row * 256) + (uint32_t)((((col >> 3) ^ (row & 7)) & 15) << 4)
         + (uint32_t)((col & 7) << 1);
}
__device__ __forceinline__ uint32_t swz16(int row, int ch) {
    return (uint32_t)(row * 256) + (uint32_t)(((ch ^ (row & 7)) & 15) << 4);
}

// smem layout: 96-row tiles. Q hi/lo; K hi/lo (K-hi becomes V-hi after S)
#define SM_QHI  0
#define SM_QLO  24576
#define SM_KVHI 49152
#define SM_KLO  73728
#define SM_IDX  98304    /* 96 ints */
#define SM_ORD  98688
#define SMEM_TOTAL 98944

// Dead-code-in-practice fallback for nc > 96 (slow, simple, correct).
__device__ __noinline__ void attn_fallback(int b, int c, int k, int nc,
                                           const int* idxs,
                                           const float* query,
                                           const float* value,
                                           float* out) {
    for (int r = threadIdx.x; r < nc; r += blockDim.x) {
        int i = idxs[r];
        const float* q = query + (((size_t)b * L_ + i) * V_ + k) * D_;
        float m = -1e30f;
        for (int jj = 0; jj < nc; jj++) {
            const float* kr = g_sumK + ((size_t)b * L_ + idxs[jj]) * D_;
            float s = 0.f;
            for (int d = 0; d < D_; d++) s += q[d] * kr[d];
            m = fmaxf(m, s * SCALE_);
        }
        float l = 0.f;
        for (int jj = 0; jj < nc; jj++) {
            const float* kr = g_sumK + ((size_t)b * L_ + idxs[jj]) * D_;
            float s = 0.f;
            for (int d = 0; d < D_; d++) s += q[d] * kr[d];
            l += __expf(s * SCALE_ - m);
        }
        for (int d0 = 0; d0 < D_; d0 += 32) {
            float acc[32];
            for (int e = 0; e < 32; e++) acc[e] = 0.f;
            for (int jj = 0; jj < nc; jj++) {
                const float* kr = g_sumK + ((size_t)b * L_ + idxs[jj]) * D_;
                float s = 0.f;
                for (int d = 0; d < D_; d++) s += q[d] * kr[d];
                float p = __expf(s * SCALE_ - m) / l;
                const float* vr = value +
                    (((size_t)b * L_ + idxs[jj]) * V_ + k) * D_ + d0;
                for (int e = 0; e < 32; e++) acc[e] += p * vr[e];
            }
            float* dst = out + (((size_t)b * L_ + i) * V_ + k) * D_ + d0;
            for (int e = 0; e < 32; e++) dst[e] = acc[e];
        }
    }
}

// ===========================================================================
// HMMA clustered attention: CTA = (head, cluster-rank). 6 warps = 6 full-N
// 16-row strips. P lives in registers (QK C-frag == PV A-frag). 2 CTAs/SM.
// ===========================================================================
extern __shared__ char smx[];

__global__ void __launch_bounds__(192, 2)
attn_mma_kernel(const float* __restrict__ query,
                const float* __restrict__ value,
                float* __restrict__ out) {
    const int k = blockIdx.x, cl = blockIdx.y;
    const int tid = threadIdx.x;
    const int lane = tid & 31;
    const int w = tid >> 5;          // 0..5 = strip

    // ---- LPT: rank clusters by descending count (deterministic tie-break)
    if (w == 0) {
        int key = -1;
        if (lane < 16) key = (g_cnt[lane >> 3][lane & 7] << 4) | (15 - lane);
        int rank = 0;
#pragma unroll
        for (int j = 0; j < 16; j++) {
            int other = __shfl_sync(0xffffffffu, key, j);
            if (lane < 16 && other > key) rank++;
        }
        if (lane < 16 && rank == cl) *(int*)(smx + SM_ORD) = lane;
    }
    __syncthreads();
    const int ordv = *(int*)(smx + SM_ORD);
    const int b = ordv >> 3, c = ordv & 7;

    const int nc = g_cnt[b][c];
    if (nc == 0) return;
    if (nc > NR_MAX) {
        attn_fallback(b, c, k, nc, g_idx[b][c], query, value, out);
        return;
    }

    int* idxs = (int*)(smx + SM_IDX);
    for (int t = tid; t < nc; t += 192) idxs[t] = g_idx[b][c][t];
    __syncthreads();

    const int nr = (nc + 15) & ~15;           // <= 96
    const int npair = nr >> 4;                // <= 6

    const uint32_t sb  = smem_u32(smx);
    const uint32_t qhi = sb + SM_QHI, qlo = sb + SM_QLO;
    const uint32_t kvh = sb + SM_KVHI, klo = sb + SM_KLO;

    // ---- K (pre-split hi/lo) via cp.async ----
    for (int t = tid; t < nr * 16; t += 192) {
        int row = t >> 4, ch = t & 15;
        uint32_t so = swz16(row, ch);
        if (row < nc) {
            size_t kb = (((size_t)b * L_ + idxs[row]) << 8) + (ch << 4);
            cpa16(kvh + so, (const char*)g_sKh + kb);
            cpa16(klo + so, (const char*)g_sKl + kb);
        } else {
            uint4 zz = make_uint4(0, 0, 0, 0);
            *(uint4*)(smx + SM_KVHI + so) = zz;
            *(uint4*)(smx + SM_KLO + so) = zz;
        }
    }
    asm volatile("cp.async.commit_group;");

    // ---- Q: direct LDG.128 (one row per warp-inst) -> split -> STS.64 ----
#pragma unroll 1
    for (int batch = 0; batch < 2; batch++) {
        float4 qv[8];
#pragma unroll
        for (int i = 0; i < 8; i++) {
            int gr = batch * 48 + w + 6 * i;
            if (gr < nc)
                qv[i] = ((const float4*)query)[
                    ((((size_t)b * L_ + idxs[gr]) * V_ + k) << 5) + lane];
        }
#pragma unroll
        for (int i = 0; i < 8; i++) {
            int lr = batch * 48 + w + 6 * i;
            uint32_t h0 = 0, l0 = 0, h1 = 0, l1 = 0;
            if (lr < nc) {
                split2(qv[i].x * SCALE_, qv[i].y * SCALE_, h0, l0);
                split2(qv[i].z * SCALE_, qv[i].w * SCALE_, h1, l1);
            }
            uint32_t off = swz(lr, lane * 4);
            *(uint2*)(smx + SM_QHI + off) = make_uint2(h0, h1);
            *(uint2*)(smx + SM_QLO + off) = make_uint2(l0, l1);
        }
    }
    asm volatile("cp.async.wait_group 0;" ::: "memory");
    __syncthreads();

    const int g  = lane >> 3;
    const int rA = (lane & 7) + ((g & 1) << 3);
    const int cA = ((g >> 1) & 1) << 3;
    const int rB = (lane & 7) + (((g >> 1) & 1) << 3);
    const int cB = (g & 1) << 3;
    const int colb = (lane & 3) << 1;
    const int qr = lane >> 2;

    const int lr0 = w * 16;
    const bool active = lr0 < nc;
    const int r1 = lr0 + qr, r2 = r1 + 8;

    // ================= S = Q * Ksum^T (3-term, full N per warp) ============
    float cS[12][4];
#pragma unroll
    for (int n = 0; n < 12; n++)
#pragma unroll
        for (int r = 0; r < 4; r++) cS[n][r] = 0.f;

    if (active) {
#pragma unroll
        for (int s = 0; s < 8; s++) {
            uint32_t ah[4], al[4], bh[6][4], bl[6][4];
            ldsm4(qhi + swz(lr0 + rA, s * 16 + cA), ah);
            ldsm4(qlo + swz(lr0 + rA, s * 16 + cA), al);
#pragma unroll
            for (int u = 0; u < 6; u++)
                if (u < npair) {
                    ldsm4(kvh + swz(16 * u + rB, s * 16 + cB), bh[u]);
                    ldsm4(klo + swz(16 * u + rB, s * 16 + cB), bl[u]);
                }
            // term-major: same-accumulator distance = 2*npair mmas
#pragma unroll
            for (int u = 0; u < 6; u++)
                if (u < npair) {
                    mma16816(cS[2 * u],     ah, bh[u][0], bh[u][1]);
                    mma16816(cS[2 * u + 1], ah, bh[u][2], bh[u][3]);
                }
#pragma unroll
            for (int u = 0; u < 6; u++)
                if (u < npair) {
                    mma16816(cS[2 * u],     ah, bl[u][0], bl[u][1]);
                    mma16816(cS[2 * u + 1], ah, bl[u][2], bl[u][3]);
                }
#pragma unroll
            for (int u = 0; u < 6; u++)
                if (u < npair) {
                    mma16816(cS[2 * u],     al, bh[u][0], bh[u][1]);
                    mma16816(cS[2 * u + 1], al, bh[u][2], bh[u][3]);
                }
        }
    }

    // ================= warp-local softmax; P -> register A-frags ===========
    uint32_t phk[6][4];
    float lt0 = 0.f, lt1 = 0.f;
    if (active) {
        float m0 = -1e30f, m1 = -1e30f;
#pragma unroll
        for (int u = 0; u < 6; u++)
            if (u < npair) {
#pragma unroll
                for (int sub = 0; sub < 2; sub++) {
                    int n = 2 * u + sub;
                    int c0 = u * 16 + sub * 8 + colb;
                    if (c0 < nc)     { m0 = fmaxf(m0, cS[n][0]); m1 = fmaxf(m1, cS[n][2]); }
                    if (c0 + 1 < nc) { m0 = fmaxf(m0, cS[n][1]); m1 = fmaxf(m1, cS[n][3]); }
                }
            }
        m0 = fmaxf(m0, __shfl_xor_sync(0xffffffffu, m0, 1));
        m0 = fmaxf(m0, __shfl_xor_sync(0xffffffffu, m0, 2));
        m1 = fmaxf(m1, __shfl_xor_sync(0xffffffffu, m1, 1));
        m1 = fmaxf(m1, __shfl_xor_sync(0xffffffffu, m1, 2));

#pragma unroll
        for (int kt = 0; kt < 6; kt++)
            if (kt < npair) {
#pragma unroll
                for (int sub = 0; sub < 2; sub++) {
                    int n = 2 * kt + sub;
                    int c0 = kt * 16 + sub * 8 + colb;
                    float p0 = (c0     < nc) ? __expf(cS[n][0] - m0) : 0.f;
                    float p1 = (c0 + 1 < nc) ? __expf(cS[n][1] - m0) : 0.f;
                    float p2 = (c0     < nc) ? __expf(cS[n][2] - m1) : 0.f;
                    float p3 = (c0 + 1 < nc) ? __expf(cS[n][3] - m1) : 0.f;
                    lt0 += p0 + p1; lt1 += p2 + p3;
                    // C-frag -> A-frag: a0/a1 = k<8 (sub0), a2/a3 = k>=8 (sub1)
                    phk[kt][2 * sub]     = packh2(p0, p1);   // row r1
                    phk[kt][2 * sub + 1] = packh2(p2, p3);   // row r2
                }
            }
        lt0 += __shfl_xor_sync(0xffffffffu, lt0, 1);
        lt0 += __shfl_xor_sync(0xffffffffu, lt0, 2);
        lt1 += __shfl_xor_sync(0xffffffffu, lt1, 1);
        lt1 += __shfl_xor_sync(0xffffffffu, lt1, 2);
    }

    // ---- V batch A LDG (before barrier: global only, hides latency) ------
    float4 va[8];
#pragma unroll
    for (int i = 0; i < 8; i++) {
        int row = w + 6 * i;              // 0..47
        if (row < nc)
            va[i] = ((const float4*)value)[
                ((((size_t)b * L_ + idxs[row]) * V_ + k) << 5) + lane];
    }
    __syncthreads();   // all warps done with K tiles

    // ---- V store (fp16 hi only) over the K-hi tile -----------------------
#pragma unroll
    for (int i = 0; i < 8; i++) {
        int row = w + 6 * i;
        uint32_t h0 = 0, h1 = 0;
        if (row < nc) {
            h0 = packh2(va[i].x, va[i].y);
            h1 = packh2(va[i].z, va[i].w);
        }
        if (row < nr)
            *(uint2*)(smx + SM_KVHI + swz(row, lane * 4)) = make_uint2(h0, h1);
    }
    {
        float4 vbB[8];
#pragma unroll
        for (int i = 0; i < 8; i++) {
            int row = 48 + w + 6 * i;     // 48..95
            if (row < nc)
                vbB[i] = ((const float4*)value)[
                    ((((size_t)b * L_ + idxs[row]) * V_ + k) << 5) + lane];
        }
#pragma unroll
        for (int i = 0; i < 8; i++) {
            int row = 48 + w + 6 * i;
            uint32_t h0 = 0, h1 = 0;
            if (row < nc) {
                h0 = packh2(vbB[i].x, vbB[i].y);
                h1 = packh2(vbB[i].z, vbB[i].w);
            }
            if (row < nr)
                *(uint2*)(smx + SM_KVHI + swz(row, lane * 4)) = make_uint2(h0, h1);
        }
    }
    __syncthreads();   // V tile complete

    // ================= O = P * Vhi (P from registers, full d) ==============
    if (active) {
        float o[16][4];
#pragma unroll
        for (int n = 0; n < 16; n++)
#pragma unroll
            for (int r = 0; r < 4; r++) o[n][r] = 0.f;

#pragma unroll
        for (int kt = 0; kt < 6; kt++)
            if (kt < npair) {
#pragma unroll
                for (int dp = 0; dp < 8; dp++) {
                    uint32_t vh[4];
                    ldsm4t(kvh + swz(16 * kt + rA, 16 * dp + cA), vh);
                    mma16816(o[2 * dp],     phk[kt], vh[0], vh[1]);
                    mma16816(o[2 * dp + 1], phk[kt], vh[2], vh[3]);
                }
            }

        // ---- epilogue
        float i0 = 1.f / lt0, i1 = 1.f / lt1;
        float* d1 = (r1 < nc)
            ? out + (((size_t)b * L_ + idxs[r1]) * V_ + k) * D_ : nullptr;
        float* d2 = (r2 < nc)
            ? out + (((size_t)b * L_ + idxs[r2]) * V_ + k) * D_ : nullptr;
#pragma unroll
        for (int n = 0; n < 16; n++) {
            int col = (n >> 1) * 16 + (n & 1) * 8 + colb;
            if (d1) *(float2*)(d1 + col) = make_float2(o[n][0] * i0, o[n][1] * i0);
            if (d2) *(float2*)(d2 + col) = make_float2(o[n][2] * i1, o[n][3] * i1);
        }
    }
}

extern "C" void kernel_launch(void* const* d_in, const int* in_sizes, int n_in,
                              void* d_out, int out_size) {
    (void)in_sizes; (void)n_in; (void)out_size;
    const float* query = (const float*)d_in[0];
    const float* key   = (const float*)d_in[1];
    const float* value = (const float*)d_in[2];
    const int*   label = (const int*)d_in[3];
    float* out = (float*)d_out;

    prep_kernel<<<1040, 256>>>((const float4*)key, label);
    cudaFuncSetAttribute(attn_mma_kernel,
                         cudaFuncAttributeMaxDynamicSharedMemorySize, SMEM_TOTAL);
    attn_mma_kernel<<<dim3(V_, 16, 1), 192, SMEM_TOTAL>>>(query, value, out);
}

// round 14
// speedup vs baseline: 1.0620x; 1.0620x over previous
#include <cuda_runtime.h>
#include <cuda_fp16.h>
#include <cstdint>

#define B_ 2
#define L_ 512
#define V_ 64
#define D_ 128
#define NC_ 8
#define NR_MAX 96

// ---- static device scratch (no allocations allowed) ----
__device__ float  g_sumK[B_ * L_ * D_];
__device__ __half g_sKh[B_ * L_ * D_];
__device__ __half g_sKl[B_ * L_ * D_];
__device__ int    g_idx[B_][NC_][L_];
__device__ int    g_cnt[B_][NC_];

#define SCALE_ 0.08838834764831845f

__device__ __forceinline__ uint32_t packh2(float a, float b2) {
    __half2 h = __halves2half2(__float2half_rn(a), __float2half_rn(b2));
    return *reinterpret_cast<uint32_t*>(&h);
}

// ===========================================================================
// Prep kernel: blocks [0,1024) sumK (+fp16 hi/lo); [1024,1040) idx lists
// ===========================================================================
__global__ void prep_kernel(const float4* __restrict__ key4,
                            const int* __restrict__ label) {
    __shared__ float4 part[256];
    const int blk = blockIdx.x;

    if (blk < 1024) {
        int bl = blk;
        int g = threadIdx.x & 31, qd = threadIdx.x >> 5;
        const float4* p = key4 + (size_t)bl * (V_ * D_ / 4)
                        + (size_t)(qd * 8) * (D_ / 4) + g;
        float4 s = make_float4(0.f, 0.f, 0.f, 0.f);
#pragma unroll
        for (int vv = 0; vv < 8; vv++) {
            float4 t = p[(size_t)vv * (D_ / 4)];
            s.x += t.x; s.y += t.y; s.z += t.z; s.w += t.w;
        }
        part[threadIdx.x] = s;
        __syncthreads();
        if (qd < 4) {
            float4 a = part[threadIdx.x], b2 = part[threadIdx.x + 128];
            part[threadIdx.x] =
                make_float4(a.x + b2.x, a.y + b2.y, a.z + b2.z, a.w + b2.w);
        }
        __syncthreads();
        if (qd == 0) {
            float4 a = part[g], b2 = part[32 + g], c2 = part[64 + g], d2 = part[96 + g];
            float4 r = make_float4(a.x + b2.x + c2.x + d2.x, a.y + b2.y + c2.y + d2.y,
                                   a.z + b2.z + c2.z + d2.z, a.w + b2.w + c2.w + d2.w);
            ((float4*)g_sumK)[(size_t)bl * 32 + g] = r;
            __half hx = __float2half_rn(r.x), hy = __float2half_rn(r.y);
            __half hz = __float2half_rn(r.z), hw = __float2half_rn(r.w);
            size_t o = (size_t)bl * 64 + g * 2;
            { __half2 t = __halves2half2(hx, hy); ((uint32_t*)g_sKh)[o] = *(uint32_t*)&t; }
            { __half2 t = __halves2half2(hz, hw); ((uint32_t*)g_sKh)[o + 1] = *(uint32_t*)&t; }
            ((uint32_t*)g_sKl)[o] =
                packh2(r.x - __half2float(hx), r.y - __half2float(hy));
            ((uint32_t*)g_sKl)[o + 1] =
                packh2(r.z - __half2float(hz), r.w - __half2float(hw));
        }
    } else {
        if (threadIdx.x >= 32) return;
        int bc = blk - 1024;
        int c = bc & 7, b = bc >> 3;
        int lane = threadIdx.x;
        int cnt = 0;
        for (int l0 = 0; l0 < L_; l0 += 32) {
            int l = l0 + lane;
            int lbl = label[b * L_ + l];
            unsigned m = __ballot_sync(0xffffffffu, lbl == c);
            if (lbl == c) {
                int pos = cnt + __popc(m & ((1u << lane) - 1u));
                g_idx[b][c][pos] = l;
            }
            cnt += __popc(m);
        }
        if (lane == 0) g_cnt[b][c] = cnt;
    }
}

// ===========================================================================
// PTX helpers (family-common, valid on target sm_103)
// ===========================================================================
__device__ __forceinline__ uint32_t smem_u32(const void* p) {
    uint32_t a;
    asm("{ .reg .u64 t; cvta.to.shared.u64 t, %1; cvt.u32.u64 %0, t; }"
        : "=r"(a) : "l"(p));
    return a;
}
__device__ __forceinline__ void cpa16(uint32_t dst, const void* src) {
    asm volatile("cp.async.cg.shared.global [%0], [%1], 16;"
                 :: "r"(dst), "l"(src));
}
__device__ __forceinline__ void ldsm4(uint32_t addr, uint32_t* r) {
    asm volatile("ldmatrix.sync.aligned.m8n8.x4.shared.b16 {%0,%1,%2,%3}, [%4];"
                 : "=r"(r[0]), "=r"(r[1]), "=r"(r[2]), "=r"(r[3]) : "r"(addr));
}
__device__ __forceinline__ void ldsm4t(uint32_t addr, uint32_t* r) {
    asm volatile("ldmatrix.sync.aligned.m8n8.x4.trans.shared.b16 {%0,%1,%2,%3}, [%4];"
                 : "=r"(r[0]), "=r"(r[1]), "=r"(r[2]), "=r"(r[3]) : "r"(addr));
}
__device__ __forceinline__ void mma16816(float* c, const uint32_t* a,
                                         uint32_t b0, uint32_t b1) {
    asm volatile(
        "mma.sync.aligned.m16n8k16.row.col.f32.f16.f16.f32 "
        "{%0,%1,%2,%3}, {%4,%5,%6,%7}, {%8,%9}, {%0,%1,%2,%3};"
        : "+f"(c[0]), "+f"(c[1]), "+f"(c[2]), "+f"(c[3])
        : "r"(a[0]), "r"(a[1]), "r"(a[2]), "r"(a[3]), "r"(b0), "r"(b1));
}
__device__ __forceinline__ void split2(float x0, float x1,
                                       uint32_t& hi, uint32_t& lo) {
    __half h0 = __float2half_rn(x0), h1 = __float2half_rn(x1);
    __half l0 = __float2half_rn(x0 - __half2float(h0));
    __half l1 = __float2half_rn(x1 - __half2float(h1));
    __half2 hp = __halves2half2(h0, h1), lp = __halves2half2(l0, l1);
    hi = *reinterpret_cast<uint32_t*>(&hp);
    lo = *reinterpret_cast<uint32_t*>(&lp);
}
// byte offset in an f16 tile (256B rows), 16B-chunk XOR swizzle
__device__ __forceinline__ uint32_t swz(int row, int col) {
    return (uint32_t)(row * 256) + (uint32_t)((((col >> 3) ^ (row & 7)) & 15) << 4)
         + (uint32_t)((col & 7) << 1);
}
__device__ __forceinline__ uint32_t swz16(int row, int ch) {
    return (uint32_t)(row * 256) + (uint32_t)(((ch ^ (row & 7)) & 15) << 4);
}

// smem layout: ONLY K hi/lo 96-row tiles (K-hi becomes V-hi after S) + idx
#define SM_KVHI 0
#define SM_KLO  24576
#define SM_IDX  49152    /* 96 ints */
#define SM_ORD  49536
#define SMEM_TOTAL 49664

// Dead-code-in-practice fallback for nc > 96 (slow, simple, correct).
__device__ __noinline__ void attn_fallback(int b, int c, int k, int nc,
                                           const int* idxs,
                                           const float* query,
                                           const float* value,
                                           float* out) {
    for (int r = threadIdx.x; r < nc; r += blockDim.x) {
        int i = idxs[r];
        const float* q = query + (((size_t)b * L_ + i) * V_ + k) * D_;
        float m = -1e30f;
        for (int jj = 0; jj < nc; jj++) {
            const float* kr = g_sumK + ((size_t)b * L_ + idxs[jj]) * D_;
            float s = 0.f;
            for (int d = 0; d < D_; d++) s += q[d] * kr[d];
            m = fmaxf(m, s * SCALE_);
        }
        float l = 0.f;
        for (int jj = 0; jj < nc; jj++) {
            const float* kr = g_sumK + ((size_t)b * L_ + idxs[jj]) * D_;
            float s = 0.f;
            for (int d = 0; d < D_; d++) s += q[d] * kr[d];
            l += __expf(s * SCALE_ - m);
        }
        for (int d0 = 0; d0 < D_; d0 += 32) {
            float acc[32];
            for (int e = 0; e < 32; e++) acc[e] = 0.f;
            for (int jj = 0; jj < nc; jj++) {
                const float* kr = g_sumK + ((size_t)b * L_ + idxs[jj]) * D_;
                float s = 0.f;
                for (int d = 0; d < D_; d++) s += q[d] * kr[d];
                float p = __expf(s * SCALE_ - m) / l;
                const float* vr = value +
                    (((size_t)b * L_ + idxs[jj]) * V_ + k) * D_ + d0;
                for (int e = 0; e < 32; e++) acc[e] += p * vr[e];
            }
            float* dst = out + (((size_t)b * L_ + i) * V_ + k) * D_ + d0;
            for (int e = 0; e < 32; e++) dst[e] = acc[e];
        }
    }
}

// ===========================================================================
// HMMA clustered attention: CTA = (head, cluster-rank). 6 warps = 6 full-N
// 16-row strips. Q A-frags straight from global (no Q smem); P in registers.
// smem = K tiles only -> 3 CTAs/SM.
// ===========================================================================
extern __shared__ char smx[];

__global__ void __launch_bounds__(192, 3)
attn_mma_kernel(const float* __restrict__ query,
                const float* __restrict__ value,
                float* __restrict__ out) {
    const int k = blockIdx.x, cl = blockIdx.y;
    const int tid = threadIdx.x;
    const int lane = tid & 31;
    const int w = tid >> 5;          // 0..5 = strip

    // ---- LPT: rank clusters by descending count (deterministic tie-break)
    if (w == 0) {
        int key = -1;
        if (lane < 16) key = (g_cnt[lane >> 3][lane & 7] << 4) | (15 - lane);
        int rank = 0;
#pragma unroll
        for (int j = 0; j < 16; j++) {
            int other = __shfl_sync(0xffffffffu, key, j);
            if (lane < 16 && other > key) rank++;
        }
        if (lane < 16 && rank == cl) *(int*)(smx + SM_ORD) = lane;
    }
    __syncthreads();
    const int ordv = *(int*)(smx + SM_ORD);
    const int b = ordv >> 3, c = ordv & 7;

    const int nc = g_cnt[b][c];
    if (nc == 0) return;
    if (nc > NR_MAX) {
        attn_fallback(b, c, k, nc, g_idx[b][c], query, value, out);
        return;
    }

    int* idxs = (int*)(smx + SM_IDX);
    for (int t = tid; t < nc; t += 192) idxs[t] = g_idx[b][c][t];
    __syncthreads();

    const int nr = (nc + 15) & ~15;           // <= 96
    const int npair = nr >> 4;                // <= 6

    const uint32_t sb  = smem_u32(smx);
    const uint32_t kvh = sb + SM_KVHI, klo = sb + SM_KLO;

    // ---- K (pre-split hi/lo) via cp.async ----
    for (int t = tid; t < nr * 16; t += 192) {
        int row = t >> 4, ch = t & 15;
        uint32_t so = swz16(row, ch);
        if (row < nc) {
            size_t kb = (((size_t)b * L_ + idxs[row]) << 8) + (ch << 4);
            cpa16(kvh + so, (const char*)g_sKh + kb);
            cpa16(klo + so, (const char*)g_sKl + kb);
        } else {
            uint4 zz = make_uint4(0, 0, 0, 0);
            *(uint4*)(smx + SM_KVHI + so) = zz;
            *(uint4*)(smx + SM_KLO + so) = zz;
        }
    }
    asm volatile("cp.async.commit_group;");
    asm volatile("cp.async.wait_group 0;" ::: "memory");
    __syncthreads();

    const int g  = lane >> 3;
    const int rB = (lane & 7) + (((g >> 1) & 1) << 3);
    const int cB = (g & 1) << 3;
    const int rA = (lane & 7) + ((g & 1) << 3);        // V-trans ldsm rows
    const int cA = ((g >> 1) & 1) << 3;
    const int colb = (lane & 3) << 1;                  // canonical A col base
    const int qr = lane >> 2;

    const int lr0 = w * 16;
    const bool active = lr0 < nc;
    const int r1 = lr0 + qr, r2 = r1 + 8;

    // Q row pointers (canonical m16n8k16 A layout: rows qr, qr+8; cols colb)
    const float* qp1 = (r1 < nc)
        ? query + (((size_t)b * L_ + idxs[r1]) * V_ + k) * D_ : nullptr;
    const float* qp2 = (r2 < nc)
        ? query + (((size_t)b * L_ + idxs[r2]) * V_ + k) * D_ : nullptr;

    // ================= S = Q * Ksum^T (3-term, full N per warp) ============
    float cS[12][4];
#pragma unroll
    for (int n = 0; n < 12; n++)
#pragma unroll
        for (int r = 0; r < 4; r++) cS[n][r] = 0.f;

    if (active) {
        const float2 z2 = make_float2(0.f, 0.f);
        // software-pipelined Q fragment loads (double buffer)
        float2 q0, q1, q2, q3, n0, n1, n2, n3;
        q0 = qp1 ? *(const float2*)(qp1 + colb) : z2;
        q1 = qp2 ? *(const float2*)(qp2 + colb) : z2;
        q2 = qp1 ? *(const float2*)(qp1 + colb + 8) : z2;
        q3 = qp2 ? *(const float2*)(qp2 + colb + 8) : z2;
#pragma unroll
        for (int s = 0; s < 8; s++) {
            if (s < 7) {
                int o = (s + 1) * 16 + colb;
                n0 = qp1 ? *(const float2*)(qp1 + o) : z2;
                n1 = qp2 ? *(const float2*)(qp2 + o) : z2;
                n2 = qp1 ? *(const float2*)(qp1 + o + 8) : z2;
                n3 = qp2 ? *(const float2*)(qp2 + o + 8) : z2;
            }
            uint32_t ah[4], al[4];
            split2(q0.x * SCALE_, q0.y * SCALE_, ah[0], al[0]);
            split2(q1.x * SCALE_, q1.y * SCALE_, ah[1], al[1]);
            split2(q2.x * SCALE_, q2.y * SCALE_, ah[2], al[2]);
            split2(q3.x * SCALE_, q3.y * SCALE_, ah[3], al[3]);
#pragma unroll
            for (int u = 0; u < 6; u++)
                if (u < npair) {
                    uint32_t bh[4], bl[4];
                    ldsm4(kvh + swz(16 * u + rB, s * 16 + cB), bh);
                    ldsm4(klo + swz(16 * u + rB, s * 16 + cB), bl);
                    mma16816(cS[2 * u],     ah, bh[0], bh[1]);
                    mma16816(cS[2 * u + 1], ah, bh[2], bh[3]);
                    mma16816(cS[2 * u],     ah, bl[0], bl[1]);
                    mma16816(cS[2 * u + 1], ah, bl[2], bl[3]);
                    mma16816(cS[2 * u],     al, bh[0], bh[1]);
                    mma16816(cS[2 * u + 1], al, bh[2], bh[3]);
                }
            q0 = n0; q1 = n1; q2 = n2; q3 = n3;
        }
    }

    // ================= warp-local softmax; P -> register A-frags ===========
    uint32_t phk[6][4];
    float lt0 = 0.f, lt1 = 0.f;
    if (active) {
        float m0 = -1e30f, m1 = -1e30f;
#pragma unroll
        for (int u = 0; u < 6; u++)
            if (u < npair) {
#pragma unroll
                for (int sub = 0; sub < 2; sub++) {
                    int n = 2 * u + sub;
                    int c0 = u * 16 + sub * 8 + colb;
                    if (c0 < nc)     { m0 = fmaxf(m0, cS[n][0]); m1 = fmaxf(m1, cS[n][2]); }
                    if (c0 + 1 < nc) { m0 = fmaxf(m0, cS[n][1]); m1 = fmaxf(m1, cS[n][3]); }
                }
            }
        m0 = fmaxf(m0, __shfl_xor_sync(0xffffffffu, m0, 1));
        m0 = fmaxf(m0, __shfl_xor_sync(0xffffffffu, m0, 2));
        m1 = fmaxf(m1, __shfl_xor_sync(0xffffffffu, m1, 1));
        m1 = fmaxf(m1, __shfl_xor_sync(0xffffffffu, m1, 2));

#pragma unroll
        for (int kt = 0; kt < 6; kt++)
            if (kt < npair) {
#pragma unroll
                for (int sub = 0; sub < 2; sub++) {
                    int n = 2 * kt + sub;
                    int c0 = kt * 16 + sub * 8 + colb;
                    float p0 = (c0     < nc) ? __expf(cS[n][0] - m0) : 0.f;
                    float p1 = (c0 + 1 < nc) ? __expf(cS[n][1] - m0) : 0.f;
                    float p2 = (c0     < nc) ? __expf(cS[n][2] - m1) : 0.f;
                    float p3 = (c0 + 1 < nc) ? __expf(cS[n][3] - m1) : 0.f;
                    lt0 += p0 + p1; lt1 += p2 + p3;
                    phk[kt][2 * sub]     = packh2(p0, p1);   // row r1, k-sub
                    phk[kt][2 * sub + 1] = packh2(p2, p3);   // row r2
                }
            }
        lt0 += __shfl_xor_sync(0xffffffffu, lt0, 1);
        lt0 += __shfl_xor_sync(0xffffffffu, lt0, 2);
        lt1 += __shfl_xor_sync(0xffffffffu, lt1, 1);
        lt1 += __shfl_xor_sync(0xffffffffu, lt1, 2);
    }

    // ---- V batch A LDG (before barrier: global only, hides latency) ------
    float4 va[8];
#pragma unroll
    for (int i = 0; i < 8; i++) {
        int row = w + 6 * i;              // 0..47
        if (row < nc)
            va[i] = ((const float4*)value)[
                ((((size_t)b * L_ + idxs[row]) * V_ + k) << 5) + lane];
    }
    __syncthreads();   // all warps done with K tiles

    // ---- V store (fp16 hi only) over the K-hi tile -----------------------
#pragma unroll
    for (int i = 0; i < 8; i++) {
        int row = w + 6 * i;
        uint32_t h0 = 0, h1 = 0;
        if (row < nc) {
            h0 = packh2(va[i].x, va[i].y);
            h1 = packh2(va[i].z, va[i].w);
        }
        if (row < nr)
            *(uint2*)(smx + SM_KVHI + swz(row, lane * 4)) = make_uint2(h0, h1);
    }
    {
        float4 vbB[8];
#pragma unroll
        for (int i = 0; i < 8; i++) {
            int row = 48 + w + 6 * i;     // 48..95
            if (row < nc)
                vbB[i] = ((const float4*)value)[
                    ((((size_t)b * L_ + idxs[row]) * V_ + k) << 5) + lane];
        }
#pragma unroll
        for (int i = 0; i < 8; i++) {
            int row = 48 + w + 6 * i;
            uint32_t h0 = 0, h1 = 0;
            if (row < nc) {
                h0 = packh2(vbB[i].x, vbB[i].y);
                h1 = packh2(vbB[i].z, vbB[i].w);
            }
            if (row < nr)
                *(uint2*)(smx + SM_KVHI + swz(row, lane * 4)) = make_uint2(h0, h1);
        }
    }
    __syncthreads();   // V tile complete

    // ================= O = P * Vhi (P from registers, full d) ==============
    if (active) {
        float o[16][4];
#pragma unroll
        for (int n = 0; n < 16; n++)
#pragma unroll
            for (int r = 0; r < 4; r++) o[n][r] = 0.f;

#pragma unroll
        for (int kt = 0; kt < 6; kt++)
            if (kt < npair) {
#pragma unroll
                for (int dp = 0; dp < 8; dp++) {
                    uint32_t vh[4];
                    ldsm4t(kvh + swz(16 * kt + rA, 16 * dp + cA), vh);
                    mma16816(o[2 * dp],     phk[kt], vh[0], vh[1]);
                    mma16816(o[2 * dp + 1], phk[kt], vh[2], vh[3]);
                }
            }

        // ---- epilogue
        float i0 = 1.f / lt0, i1 = 1.f / lt1;
        float* d1 = (r1 < nc)
            ? out + (((size_t)b * L_ + idxs[r1]) * V_ + k) * D_ : nullptr;
        float* d2 = (r2 < nc)
            ? out + (((size_t)b * L_ + idxs[r2]) * V_ + k) * D_ : nullptr;
#pragma unroll
        for (int n = 0; n < 16; n++) {
            int col = (n >> 1) * 16 + (n & 1) * 8 + colb;
            if (d1) *(float2*)(d1 + col) = make_float2(o[n][0] * i0, o[n][1] * i0);
            if (d2) *(float2*)(d2 + col) = make_float2(o[n][2] * i1, o[n][3] * i1);
        }
    }
}

extern "C" void kernel_launch(void* const* d_in, const int* in_sizes, int n_in,
                              void* d_out, int out_size) {
    (void)in_sizes; (void)n_in; (void)out_size;
    const float* query = (const float*)d_in[0];
    const float* key   = (const float*)d_in[1];
    const float* value = (const float*)d_in[2];
    const int*   label = (const int*)d_in[3];
    float* out = (float*)d_out;

    prep_kernel<<<1040, 256>>>((const float4*)key, label);
    cudaFuncSetAttribute(attn_mma_kernel,
                         cudaFuncAttributeMaxDynamicSharedMemorySize, SMEM_TOTAL);
    attn_mma_kernel<<<dim3(V_, 16, 1), 192, SMEM_TOTAL>>>(query, value, out);
}